// round 10
// baseline (speedup 1.0000x reference)
#include <cuda_runtime.h>

// 3-layer LSTM (H=48) over T=262144, batch 1, + PReLU/Linear/tanh head.
//
// R9: named-barrier pipelined layers with double-buffered h.
// One persistent CTA, 480 threads:
//   grp0: tid [0,96)    -> layer 0, TWO gate rows/thread (48-wide hh dots)
//   grp1: tid [96,288)  -> layer 1, one row/thread (48 ih + 48 hh)
//   grp2: tid [288,480) -> layer 2, same
// Per iteration k (group l computes t = k - l):
//   A: matvec + activation -> s_gate[l];  bar G_l (group-local)
//   B: 48 updater threads: c,h update -> s_h[p^1][l];  bar H (pairwise l,l+1)
// Double-buffered s_h removes WAR; group-local + pairwise barriers let each
// group's B phase overlap other groups' A phases.
// z0[t] = W_ih0@x_t + b_ih0 + b_hh0 precomputed by a parallel pre-pass
// (padded with 8 zeroed steps so the in-loop prefetch needs no clamp).

typedef unsigned long long ull;

#define HN    48
#define GATES 192
#define NT    480
#define TMAX  262144

__device__ float g_z[(size_t)(TMAX + 8) * GATES];

__device__ __forceinline__ void fma2(ull &acc, ull a, ull b) {
    asm("fma.rn.f32x2 %0, %1, %2, %0;" : "+l"(acc) : "l"(a), "l"(b));
}
__device__ __forceinline__ ull add2(ull a, ull b) {
    ull r; asm("add.rn.f32x2 %0, %1, %2;" : "=l"(r) : "l"(a), "l"(b)); return r;
}
__device__ __forceinline__ float pairsum(ull a) {
    return __int_as_float((unsigned)a) + __int_as_float((unsigned)(a >> 32));
}
__device__ __forceinline__ float sigm(float x) {
    float e; asm("ex2.approx.f32 %0, %1;" : "=f"(e) : "f"(-1.4426950408889634f * x));
    float r; asm("rcp.approx.f32 %0, %1;" : "=f"(r) : "f"(1.0f + e));
    return r;
}
__device__ __forceinline__ float tanh_(float x) {
    float e; asm("ex2.approx.f32 %0, %1;" : "=f"(e) : "f"(2.8853900817779268f * x));
    float r; asm("rcp.approx.f32 %0, %1;" : "=f"(r) : "f"(1.0f + e));
    return fmaf(-2.0f, r, 1.0f);
}

// named barriers (ids 1..5; __syncthreads keeps id 0)
#define BAR_G0() asm volatile("bar.sync 1, 96;"  ::: "memory")
#define BAR_G1() asm volatile("bar.sync 2, 192;" ::: "memory")
#define BAR_G2() asm volatile("bar.sync 3, 192;" ::: "memory")
#define BAR_H0() asm volatile("bar.sync 4, 288;" ::: "memory")   // grp0 + grp1
#define BAR_H1() asm volatile("bar.sync 5, 384;" ::: "memory")   // grp1 + grp2

// ---------------- pre-pass ----------------
__global__ void zprep_kernel(const float* __restrict__ x, int T,
                             const float* __restrict__ Wih0,
                             const float* __restrict__ bih0,
                             const float* __restrict__ bhh0)
{
    int t = blockIdx.x;
    int g = threadIdx.x;
    float acc = 0.0f;
    if (t < T) {
        const float* xr = x + t * 5;
        const float* w  = Wih0 + g * 5;
        acc = bih0[g] + bhh0[g];
        acc = fmaf(w[0], xr[0], acc);
        acc = fmaf(w[1], xr[1], acc);
        acc = fmaf(w[2], xr[2], acc);
        acc = fmaf(w[3], xr[3], acc);
        acc = fmaf(w[4], xr[4], acc);
    }
    g_z[(size_t)t * GATES + g] = acc;   // pad rows [T, T+8) get 0
}

// ---------------- sequential pipelined LSTM ----------------
__global__ __launch_bounds__(NT, 1)
void lstm3_pipe(const float* __restrict__ Whh0,
                const float* __restrict__ Wih1, const float* __restrict__ Whh1,
                const float* __restrict__ bih1, const float* __restrict__ bhh1,
                const float* __restrict__ Wih2, const float* __restrict__ Whh2,
                const float* __restrict__ bih2, const float* __restrict__ bhh2,
                const float* __restrict__ prelu_a,
                const float* __restrict__ l1W, const float* __restrict__ l1b,
                const float* __restrict__ l2W, const float* __restrict__ l2b,
                float* __restrict__ out, int T)
{
    __shared__ __align__(16) float s_h[2][3][HN];     // [parity][layer][j]
    __shared__ __align__(16) float s_gate[3][GATES];

    const int tid = threadIdx.x;
    const int grp = (tid < 96) ? 0 : ((tid < 288) ? 1 : 2);

    ull wA[24], wB[24];
    float bias = 0.0f;
    int rowA = 0, rowB = 0, row = 0;

    if (grp == 0) {
        rowA = tid;          // rows [0,96): i/f (sigmoid)
        rowB = tid + 96;     // rows [96,192): g (tanh) if tid<48 else o
        const ull* p = (const ull*)(Whh0 + rowA * 48);
        #pragma unroll
        for (int q = 0; q < 24; q++) wA[q] = p[q];
        p = (const ull*)(Whh0 + rowB * 48);
        #pragma unroll
        for (int q = 0; q < 24; q++) wB[q] = p[q];
    } else {
        row = tid - (grp == 1 ? 96 : 288);
        const float* Wih = (grp == 1) ? Wih1 : Wih2;
        const float* Whh = (grp == 1) ? Whh1 : Whh2;
        const ull* p = (const ull*)(Wih + row * 48);
        #pragma unroll
        for (int q = 0; q < 24; q++) wA[q] = p[q];
        p = (const ull*)(Whh + row * 48);
        #pragma unroll
        for (int q = 0; q < 24; q++) wB[q] = p[q];
        bias = (grp == 1) ? (bih1[row] + bhh1[row]) : (bih2[row] + bhh2[row]);
    }

    if (tid < 2 * 3 * HN) (&s_h[0][0][0])[tid] = 0.0f;
    __syncthreads();

    const int K = ((T + 2) + 1) & ~1;   // even iteration count, covers drain
    float c = 0.0f;

    if (grp == 0) {
        // ---------------- layer 0 loop ----------------
        const ulonglong2* rd0 = (const ulonglong2*)&s_h[0][0][0];
        const ulonglong2* rd1 = (const ulonglong2*)&s_h[1][0][0];
        float* hw0 = &s_h[1][0][0];     // step parity 0 writes buf 1
        float* hw1 = &s_h[0][0][0];
        const bool  isgB = (tid < 48);  // rowB in [96,144) = tanh gate
        const float bSc  = isgB ? 2.0f : 1.0f;
        const float bMul = isgB ? 2.0f : 1.0f;
        const float bAdd = isgB ? -1.0f : 0.0f;

        float zA0 = g_z[rowA],         zB0 = g_z[rowB];
        float zA1 = g_z[GATES + rowA], zB1 = g_z[GATES + rowB];
        const float* zp = g_z + 2 * GATES + rowA;   // t = k+2 prefetch

        for (int k = 0; k < K; k += 2) {
            // ---- even step ----
            {
                ull a0 = 0ull, a1 = 0ull, b0 = 0ull, b1 = 0ull;
                #pragma unroll
                for (int q = 0; q < 12; q++) {
                    ulonglong2 v = rd0[q];
                    fma2(a0, wA[2 * q],     v.x);
                    fma2(a1, wA[2 * q + 1], v.y);
                    fma2(b0, wB[2 * q],     v.x);
                    fma2(b1, wB[2 * q + 1], v.y);
                }
                float gA = pairsum(add2(a0, a1)) + zA0;
                float gB = pairsum(add2(b0, b1)) + zB0;
                s_gate[0][rowA] = sigm(gA);
                float sv = sigm(bSc * gB);
                s_gate[0][rowB] = fmaf(bMul, sv, bAdd);
                zA0 = zp[0]; zB0 = zp[96];              // prefetch t=k+2
                BAR_G0();
                if (tid < HN && k < T) {
                    float gi = s_gate[0][tid],          gf = s_gate[0][HN + tid];
                    float gg = s_gate[0][2 * HN + tid], go = s_gate[0][3 * HN + tid];
                    c = fmaf(gf, c, gi * gg);
                    hw0[tid] = go * tanh_(c);
                }
                BAR_H0();
            }
            // ---- odd step ----
            {
                ull a0 = 0ull, a1 = 0ull, b0 = 0ull, b1 = 0ull;
                #pragma unroll
                for (int q = 0; q < 12; q++) {
                    ulonglong2 v = rd1[q];
                    fma2(a0, wA[2 * q],     v.x);
                    fma2(a1, wA[2 * q + 1], v.y);
                    fma2(b0, wB[2 * q],     v.x);
                    fma2(b1, wB[2 * q + 1], v.y);
                }
                float gA = pairsum(add2(a0, a1)) + zA1;
                float gB = pairsum(add2(b0, b1)) + zB1;
                s_gate[0][rowA] = sigm(gA);
                float sv = sigm(bSc * gB);
                s_gate[0][rowB] = fmaf(bMul, sv, bAdd);
                zA1 = zp[GATES]; zB1 = zp[GATES + 96];  // prefetch t=k+3
                zp += 2 * GATES;
                BAR_G0();
                if (tid < HN && (k + 1) < T) {
                    float gi = s_gate[0][tid],          gf = s_gate[0][HN + tid];
                    float gg = s_gate[0][2 * HN + tid], go = s_gate[0][3 * HN + tid];
                    c = fmaf(gf, c, gi * gg);
                    hw1[tid] = go * tanh_(c);
                }
                BAR_H0();
            }
        }
    } else if (grp == 1) {
        // ---------------- layer 1 loop ----------------
        const ulonglong2* rA0 = (const ulonglong2*)&s_h[0][0][0];
        const ulonglong2* rB0 = (const ulonglong2*)&s_h[0][1][0];
        const ulonglong2* rA1 = (const ulonglong2*)&s_h[1][0][0];
        const ulonglong2* rB1 = (const ulonglong2*)&s_h[1][1][0];
        float* hw0 = &s_h[1][1][0];
        float* hw1 = &s_h[0][1][0];
        const bool  isg  = (row >= 96 && row < 144);
        const float aSc  = isg ? 2.0f : 1.0f;
        const float aMul = isg ? 2.0f : 1.0f;
        const float aAdd = isg ? -1.0f : 0.0f;

        for (int k = 0; k < K; k += 2) {
            {
                ull a0 = 0ull, a1 = 0ull, b0 = 0ull, b1 = 0ull;
                #pragma unroll
                for (int q = 0; q < 12; q++) {
                    ulonglong2 v = rA0[q];
                    ulonglong2 w = rB0[q];
                    fma2(a0, wA[2 * q],     v.x);
                    fma2(a1, wA[2 * q + 1], v.y);
                    fma2(b0, wB[2 * q],     w.x);
                    fma2(b1, wB[2 * q + 1], w.y);
                }
                float g = pairsum(add2(add2(a0, a1), add2(b0, b1))) + bias;
                float sv = sigm(aSc * g);
                s_gate[1][row] = fmaf(aMul, sv, aAdd);
                BAR_G1();
                int tg = k - 1;
                if (row < HN && (unsigned)tg < (unsigned)T) {
                    float gi = s_gate[1][row],          gf = s_gate[1][HN + row];
                    float gg = s_gate[1][2 * HN + row], go = s_gate[1][3 * HN + row];
                    c = fmaf(gf, c, gi * gg);
                    hw0[row] = go * tanh_(c);
                }
                BAR_H0();
                BAR_H1();
            }
            {
                ull a0 = 0ull, a1 = 0ull, b0 = 0ull, b1 = 0ull;
                #pragma unroll
                for (int q = 0; q < 12; q++) {
                    ulonglong2 v = rA1[q];
                    ulonglong2 w = rB1[q];
                    fma2(a0, wA[2 * q],     v.x);
                    fma2(a1, wA[2 * q + 1], v.y);
                    fma2(b0, wB[2 * q],     w.x);
                    fma2(b1, wB[2 * q + 1], w.y);
                }
                float g = pairsum(add2(add2(a0, a1), add2(b0, b1))) + bias;
                float sv = sigm(aSc * g);
                s_gate[1][row] = fmaf(aMul, sv, aAdd);
                BAR_G1();
                int tg = k;                                  // (k+1)-1
                if (row < HN && (unsigned)tg < (unsigned)T) {
                    float gi = s_gate[1][row],          gf = s_gate[1][HN + row];
                    float gg = s_gate[1][2 * HN + row], go = s_gate[1][3 * HN + row];
                    c = fmaf(gf, c, gi * gg);
                    hw1[row] = go * tanh_(c);
                }
                BAR_H0();
                BAR_H1();
            }
        }
    } else {
        // ---------------- layer 2 loop ----------------
        const ulonglong2* rA0 = (const ulonglong2*)&s_h[0][1][0];
        const ulonglong2* rB0 = (const ulonglong2*)&s_h[0][2][0];
        const ulonglong2* rA1 = (const ulonglong2*)&s_h[1][1][0];
        const ulonglong2* rB1 = (const ulonglong2*)&s_h[1][2][0];
        float* hw0 = &s_h[1][2][0];
        float* hw1 = &s_h[0][2][0];
        const bool  isg  = (row >= 96 && row < 144);
        const float aSc  = isg ? 2.0f : 1.0f;
        const float aMul = isg ? 2.0f : 1.0f;
        const float aAdd = isg ? -1.0f : 0.0f;

        for (int k = 0; k < K; k += 2) {
            {
                ull a0 = 0ull, a1 = 0ull, b0 = 0ull, b1 = 0ull;
                #pragma unroll
                for (int q = 0; q < 12; q++) {
                    ulonglong2 v = rA0[q];
                    ulonglong2 w = rB0[q];
                    fma2(a0, wA[2 * q],     v.x);
                    fma2(a1, wA[2 * q + 1], v.y);
                    fma2(b0, wB[2 * q],     w.x);
                    fma2(b1, wB[2 * q + 1], w.y);
                }
                float g = pairsum(add2(add2(a0, a1), add2(b0, b1))) + bias;
                float sv = sigm(aSc * g);
                s_gate[2][row] = fmaf(aMul, sv, aAdd);
                BAR_G2();
                int tg = k - 2;
                if (row < HN && (unsigned)tg < (unsigned)T) {
                    float gi = s_gate[2][row],          gf = s_gate[2][HN + row];
                    float gg = s_gate[2][2 * HN + row], go = s_gate[2][3 * HN + row];
                    c = fmaf(gf, c, gi * gg);
                    hw0[row] = go * tanh_(c);
                }
                BAR_H1();
            }
            {
                ull a0 = 0ull, a1 = 0ull, b0 = 0ull, b1 = 0ull;
                #pragma unroll
                for (int q = 0; q < 12; q++) {
                    ulonglong2 v = rA1[q];
                    ulonglong2 w = rB1[q];
                    fma2(a0, wA[2 * q],     v.x);
                    fma2(a1, wA[2 * q + 1], v.y);
                    fma2(b0, wB[2 * q],     w.x);
                    fma2(b1, wB[2 * q + 1], w.y);
                }
                float g = pairsum(add2(add2(a0, a1), add2(b0, b1))) + bias;
                float sv = sigm(aSc * g);
                s_gate[2][row] = fmaf(aMul, sv, aAdd);
                BAR_G2();
                int tg = k - 1;
                if (row < HN && (unsigned)tg < (unsigned)T) {
                    float gi = s_gate[2][row],          gf = s_gate[2][HN + row];
                    float gg = s_gate[2][2 * HN + row], go = s_gate[2][3 * HN + row];
                    c = fmaf(gf, c, gi * gg);
                    hw1[row] = go * tanh_(c);
                }
                BAR_H1();
            }
        }
    }

    __syncthreads();

    // ---- head: PReLU -> lin1 -> flatten -> lin2 -> tanh ----
    if (tid == 0) {
        float a = prelu_a[0];
        float v[6];
        #pragma unroll
        for (int l = 0; l < 3; l++) {
            int pb = ((T - 1 + l) & 1) ^ 1;   // parity buffer holding final h_l
            #pragma unroll
            for (int kk = 0; kk < 2; kk++) {
                float acc = l1b[kk];
                #pragma unroll
                for (int j = 0; j < HN; j++) {
                    float hv = s_h[pb][l][j];
                    hv = hv > 0.0f ? hv : a * hv;
                    acc = fmaf(hv, l1W[kk * HN + j], acc);
                }
                v[l * 2 + kk] = acc;
            }
        }
        #pragma unroll
        for (int kk = 0; kk < 2; kk++) {
            float acc = l2b[kk];
            #pragma unroll
            for (int m = 0; m < 6; m++) acc = fmaf(l2W[kk * 6 + m], v[m], acc);
            out[kk] = tanh_(acc);
        }
    }
}

extern "C" void kernel_launch(void* const* d_in, const int* in_sizes, int n_in,
                              void* d_out, int out_size) {
    int T = in_sizes[0] / 5;       // x is [1, T, 5]
    if (T > TMAX) T = TMAX;

    zprep_kernel<<<T + 8, GATES>>>(
        (const float*)d_in[0], T,
        (const float*)d_in[1],           // W_ih0
        (const float*)d_in[3],           // b_ih0
        (const float*)d_in[4]);          // b_hh0

    lstm3_pipe<<<1, NT>>>(
        (const float*)d_in[2],           // W_hh0
        (const float*)d_in[5],  (const float*)d_in[6],   // W_ih1, W_hh1
        (const float*)d_in[7],  (const float*)d_in[8],   // b_ih1, b_hh1
        (const float*)d_in[9],  (const float*)d_in[10],  // W_ih2, W_hh2
        (const float*)d_in[11], (const float*)d_in[12],  // b_ih2, b_hh2
        (const float*)d_in[13],                          // prelu_a
        (const float*)d_in[14], (const float*)d_in[15],  // lin1_W, lin1_b
        (const float*)d_in[16], (const float*)d_in[17],  // lin2_W, lin2_b
        (float*)d_out, T);
}

// round 11
// speedup vs baseline: 1.1040x; 1.1040x over previous
#include <cuda_runtime.h>

// 3-layer LSTM (H=48) over T=262144, batch 1, + PReLU/Linear/tanh head.
//
// R10: quad-mapped gates, ONE barrier per step.
// 512 threads (16 warps), grp assignment:
//   grp0: tid [0,96)    layer 0: thread 2e+s owns rows {e+48s, 96+e+48s} (i/f and g/o of element e)
//   grp1: tid [96,288)  layer 1: thread u owns row gate*48+e (e=u>>2, gate=u&3)
//   grp2: tid [288,480) layer 2: same mapping
//   tid [480,512): idle warp (barrier participation only)
// All 4 gates of element e live in adjacent lanes of one warp -> gate exchange
// is STS + __syncwarp + LDS.128 (no CTA barrier). Every quad thread keeps a
// redundant copy of c_e; lane s==0 / gate==0 writes h_e. Double-buffered s_h
// by iteration parity; a single __syncthreads per step.
// z0[t] = W_ih0@x_t + b_ih0 + b_hh0 precomputed by a parallel pre-pass.

typedef unsigned long long ull;

#define HN    48
#define GATES 192
#define NT    512
#define TMAX  262144

__device__ float g_z[(size_t)(TMAX + 8) * GATES];

__device__ __forceinline__ void fma2(ull &acc, ull a, ull b) {
    asm("fma.rn.f32x2 %0, %1, %2, %0;" : "+l"(acc) : "l"(a), "l"(b));
}
__device__ __forceinline__ ull add2(ull a, ull b) {
    ull r; asm("add.rn.f32x2 %0, %1, %2;" : "=l"(r) : "l"(a), "l"(b)); return r;
}
__device__ __forceinline__ float pairsum(ull a) {
    return __int_as_float((unsigned)a) + __int_as_float((unsigned)(a >> 32));
}
__device__ __forceinline__ float sigm(float x) {
    float e; asm("ex2.approx.f32 %0, %1;" : "=f"(e) : "f"(-1.4426950408889634f * x));
    float r; asm("rcp.approx.f32 %0, %1;" : "=f"(r) : "f"(1.0f + e));
    return r;
}
__device__ __forceinline__ float tanh_(float x) {
    float e; asm("ex2.approx.f32 %0, %1;" : "=f"(e) : "f"(2.8853900817779268f * x));
    float r; asm("rcp.approx.f32 %0, %1;" : "=f"(r) : "f"(1.0f + e));
    return fmaf(-2.0f, r, 1.0f);
}

// ---------------- pre-pass ----------------
__global__ void zprep_kernel(const float* __restrict__ x, int T,
                             const float* __restrict__ Wih0,
                             const float* __restrict__ bih0,
                             const float* __restrict__ bhh0)
{
    int t = blockIdx.x;
    int g = threadIdx.x;
    float acc = 0.0f;
    if (t < T) {
        const float* xr = x + t * 5;
        const float* w  = Wih0 + g * 5;
        acc = bih0[g] + bhh0[g];
        acc = fmaf(w[0], xr[0], acc);
        acc = fmaf(w[1], xr[1], acc);
        acc = fmaf(w[2], xr[2], acc);
        acc = fmaf(w[3], xr[3], acc);
        acc = fmaf(w[4], xr[4], acc);
    }
    g_z[(size_t)t * GATES + g] = acc;   // pad rows [T, T+8) get 0
}

// ---------------- sequential pipelined LSTM ----------------
__global__ __launch_bounds__(NT, 1)
void lstm3_pipe(const float* __restrict__ Whh0,
                const float* __restrict__ Wih1, const float* __restrict__ Whh1,
                const float* __restrict__ bih1, const float* __restrict__ bhh1,
                const float* __restrict__ Wih2, const float* __restrict__ Whh2,
                const float* __restrict__ bih2, const float* __restrict__ bhh2,
                const float* __restrict__ prelu_a,
                const float* __restrict__ l1W, const float* __restrict__ l1b,
                const float* __restrict__ l2W, const float* __restrict__ l2b,
                float* __restrict__ out, int T)
{
    __shared__ __align__(16) float s_h[2][3][HN];        // [parity][layer][e]
    __shared__ __align__(16) float s_gate[3][4 * HN];    // [layer][e*4 + slot] slot:0=i,1=f,2=g,3=o

    const int tid = threadIdx.x;

    if (tid < 2 * 3 * HN) (&s_h[0][0][0])[tid] = 0.0f;
    __syncthreads();

    const int K = (T + 3) & ~1;          // even, >= T+2 (pipeline drain)
    float c = 0.0f;

    if (tid < 96) {
        // ================= layer 0 =================
        const int e = tid >> 1, s = tid & 1;
        const int rowA = e + s * 48;          // i (s=0) or f (s=1): sigmoid
        const int rowB = 96 + e + s * 48;     // g (s=0, tanh) or o (s=1, sigmoid)
        ull wA[24], wB[24];
        {
            const ull* p = (const ull*)(Whh0 + rowA * 48);
            #pragma unroll
            for (int q = 0; q < 24; q++) wA[q] = p[q];
            p = (const ull*)(Whh0 + rowB * 48);
            #pragma unroll
            for (int q = 0; q < 24; q++) wB[q] = p[q];
        }
        const float bSc  = (s == 0) ? 2.0f : 1.0f;
        const float bMul = (s == 0) ? 2.0f : 1.0f;
        const float bAdd = (s == 0) ? -1.0f : 0.0f;

        float* gq = &s_gate[0][e * 4];
        const ulonglong2* rd0 = (const ulonglong2*)&s_h[0][0][0];
        const ulonglong2* rd1 = (const ulonglong2*)&s_h[1][0][0];
        float* hw0 = &s_h[1][0][0];
        float* hw1 = &s_h[0][0][0];

        float zA0 = g_z[rowA],         zB0 = g_z[rowB];
        float zA1 = g_z[GATES + rowA], zB1 = g_z[GATES + rowB];
        const float* zpA = g_z + 2 * GATES + rowA;
        const float* zpB = g_z + 2 * GATES + rowB;

        for (int k = 0; k < K; k += 2) {
            {   // even step: read parity 0, write parity 1
                ull a0 = 0ull, a1 = 0ull, b0 = 0ull, b1 = 0ull;
                #pragma unroll
                for (int q = 0; q < 12; q++) {
                    ulonglong2 v = rd0[q];
                    fma2(a0, wA[2 * q],     v.x);
                    fma2(a1, wA[2 * q + 1], v.y);
                    fma2(b0, wB[2 * q],     v.x);
                    fma2(b1, wB[2 * q + 1], v.y);
                }
                float gA = pairsum(add2(a0, a1)) + zA0;
                float gB = pairsum(add2(b0, b1)) + zB0;
                gq[s]     = sigm(gA);
                float sv  = sigm(bSc * gB);
                gq[2 + s] = fmaf(bMul, sv, bAdd);
                zA0 = zpA[0]; zB0 = zpB[0];                 // prefetch t=k+2
                __syncwarp();
                float4 qv = *(const float4*)gq;             // (i,f,g,o)
                if (k < T) {
                    c = fmaf(qv.y, c, qv.x * qv.z);
                    if (s == 0) hw0[e] = qv.w * tanh_(c);
                }
                __syncthreads();
            }
            {   // odd step
                ull a0 = 0ull, a1 = 0ull, b0 = 0ull, b1 = 0ull;
                #pragma unroll
                for (int q = 0; q < 12; q++) {
                    ulonglong2 v = rd1[q];
                    fma2(a0, wA[2 * q],     v.x);
                    fma2(a1, wA[2 * q + 1], v.y);
                    fma2(b0, wB[2 * q],     v.x);
                    fma2(b1, wB[2 * q + 1], v.y);
                }
                float gA = pairsum(add2(a0, a1)) + zA1;
                float gB = pairsum(add2(b0, b1)) + zB1;
                gq[s]     = sigm(gA);
                float sv  = sigm(bSc * gB);
                gq[2 + s] = fmaf(bMul, sv, bAdd);
                zA1 = zpA[GATES]; zB1 = zpB[GATES];         // prefetch t=k+3
                zpA += 2 * GATES; zpB += 2 * GATES;
                __syncwarp();
                float4 qv = *(const float4*)gq;
                if ((k + 1) < T) {
                    c = fmaf(qv.y, c, qv.x * qv.z);
                    if (s == 0) hw1[e] = qv.w * tanh_(c);
                }
                __syncthreads();
            }
        }
    } else if (tid < 480) {
        // ================= layers 1 & 2 =================
        const int grp = (tid < 288) ? 1 : 2;
        const int u   = tid - (grp == 1 ? 96 : 288);
        const int e   = u >> 2, gate = u & 3;
        const int row = gate * 48 + e;

        ull wA[24], wB[24];
        float bias;
        {
            const float* Wih = (grp == 1) ? Wih1 : Wih2;
            const float* Whh = (grp == 1) ? Whh1 : Whh2;
            const ull* p = (const ull*)(Wih + row * 48);
            #pragma unroll
            for (int q = 0; q < 24; q++) wA[q] = p[q];
            p = (const ull*)(Whh + row * 48);
            #pragma unroll
            for (int q = 0; q < 24; q++) wB[q] = p[q];
            bias = (grp == 1) ? (bih1[row] + bhh1[row]) : (bih2[row] + bhh2[row]);
        }
        const bool  isg  = (gate == 2);
        const float aSc  = isg ? 2.0f : 1.0f;
        const float aMul = isg ? 2.0f : 1.0f;
        const float aAdd = isg ? -1.0f : 0.0f;

        float* gq = &s_gate[grp][e * 4];
        const ulonglong2* rA0 = (const ulonglong2*)&s_h[0][grp - 1][0];
        const ulonglong2* rB0 = (const ulonglong2*)&s_h[0][grp][0];
        const ulonglong2* rA1 = (const ulonglong2*)&s_h[1][grp - 1][0];
        const ulonglong2* rB1 = (const ulonglong2*)&s_h[1][grp][0];
        float* hw0 = &s_h[1][grp][0];
        float* hw1 = &s_h[0][grp][0];

        for (int k = 0; k < K; k += 2) {
            {   // even step: t = k - grp
                ull a0 = 0ull, a1 = 0ull, b0 = 0ull, b1 = 0ull;
                #pragma unroll
                for (int q = 0; q < 12; q++) {
                    ulonglong2 v = rA0[q];
                    ulonglong2 w = rB0[q];
                    fma2(a0, wA[2 * q],     v.x);
                    fma2(a1, wA[2 * q + 1], v.y);
                    fma2(b0, wB[2 * q],     w.x);
                    fma2(b1, wB[2 * q + 1], w.y);
                }
                float g  = pairsum(add2(add2(a0, a1), add2(b0, b1))) + bias;
                float sv = sigm(aSc * g);
                gq[gate] = fmaf(aMul, sv, aAdd);
                __syncwarp();
                float4 qv = *(const float4*)gq;
                int tg = k - grp;
                if ((unsigned)tg < (unsigned)T) {
                    c = fmaf(qv.y, c, qv.x * qv.z);
                    if (gate == 0) hw0[e] = qv.w * tanh_(c);
                }
                __syncthreads();
            }
            {   // odd step: t = k + 1 - grp
                ull a0 = 0ull, a1 = 0ull, b0 = 0ull, b1 = 0ull;
                #pragma unroll
                for (int q = 0; q < 12; q++) {
                    ulonglong2 v = rA1[q];
                    ulonglong2 w = rB1[q];
                    fma2(a0, wA[2 * q],     v.x);
                    fma2(a1, wA[2 * q + 1], v.y);
                    fma2(b0, wB[2 * q],     w.x);
                    fma2(b1, wB[2 * q + 1], w.y);
                }
                float g  = pairsum(add2(add2(a0, a1), add2(b0, b1))) + bias;
                float sv = sigm(aSc * g);
                gq[gate] = fmaf(aMul, sv, aAdd);
                __syncwarp();
                float4 qv = *(const float4*)gq;
                int tg = k + 1 - grp;
                if ((unsigned)tg < (unsigned)T) {
                    c = fmaf(qv.y, c, qv.x * qv.z);
                    if (gate == 0) hw1[e] = qv.w * tanh_(c);
                }
                __syncthreads();
            }
        }
    } else {
        // idle warp: participate in barriers only
        for (int k = 0; k < K; k += 2) {
            __syncthreads();
            __syncthreads();
        }
    }

    __syncthreads();

    // ---- head: PReLU -> lin1 -> flatten -> lin2 -> tanh ----
    if (tid == 0) {
        float a = prelu_a[0];
        float v[6];
        #pragma unroll
        for (int l = 0; l < 3; l++) {
            int pb = ((T - 1 + l) & 1) ^ 1;   // parity buffer holding final h_l
            #pragma unroll
            for (int kk = 0; kk < 2; kk++) {
                float acc = l1b[kk];
                #pragma unroll
                for (int j = 0; j < HN; j++) {
                    float hv = s_h[pb][l][j];
                    hv = hv > 0.0f ? hv : a * hv;
                    acc = fmaf(hv, l1W[kk * HN + j], acc);
                }
                v[l * 2 + kk] = acc;
            }
        }
        #pragma unroll
        for (int kk = 0; kk < 2; kk++) {
            float acc = l2b[kk];
            #pragma unroll
            for (int m = 0; m < 6; m++) acc = fmaf(l2W[kk * 6 + m], v[m], acc);
            out[kk] = tanh_(acc);
        }
    }
}

extern "C" void kernel_launch(void* const* d_in, const int* in_sizes, int n_in,
                              void* d_out, int out_size) {
    int T = in_sizes[0] / 5;       // x is [1, T, 5]
    if (T > TMAX) T = TMAX;

    zprep_kernel<<<T + 8, GATES>>>(
        (const float*)d_in[0], T,
        (const float*)d_in[1],           // W_ih0
        (const float*)d_in[3],           // b_ih0
        (const float*)d_in[4]);          // b_hh0

    lstm3_pipe<<<1, NT>>>(
        (const float*)d_in[2],           // W_hh0
        (const float*)d_in[5],  (const float*)d_in[6],   // W_ih1, W_hh1
        (const float*)d_in[7],  (const float*)d_in[8],   // b_ih1, b_hh1
        (const float*)d_in[9],  (const float*)d_in[10],  // W_ih2, W_hh2
        (const float*)d_in[11], (const float*)d_in[12],  // b_ih2, b_hh2
        (const float*)d_in[13],                          // prelu_a
        (const float*)d_in[14], (const float*)d_in[15],  // lin1_W, lin1_b
        (const float*)d_in[16], (const float*)d_in[17],  // lin2_W, lin2_b
        (float*)d_out, T);
}